// round 1
// baseline (speedup 1.0000x reference)
#include <cuda_runtime.h>
#include <cuda_bf16.h>

// Problem constants
#define BATCH      32768
#define INPUT_DIM  256
#define NNEUR      128
#define NDEG       8            // D+1 coefficients per input dim
#define NFEAT      (INPUT_DIM * NDEG)   // 2048

// Transformed + packed coefficient table (8 KB), produced by kan_prep.
// Layout: 512 float4 "granules". Granule linear index m in [0,512):
//   m = (q*4 + gj)*32 + lane   where lane in [0,32), q in [0,4), gj in [0,4)
// Lane `lane` owns inputs i = lane*8 .. lane*8+7, i.e. pairs p = lane*4+q,
// pair p = inputs (2p, 2p+1). Granule gj of a pair holds coefficients
// (c_{2gj}, c_{2gj+1}) for both inputs of the pair, interleaved as two float2:
//   [ c_{2gj}(i0), c_{2gj}(i1), c_{2gj+1}(i0), c_{2gj+1}(i1) ]
// Coefficient order c_0..c_7 = e0,e1,e2,e3,o0,o1,o2,o3 (even/odd Horner basis).
__device__ float g_pack[NFEAT];

// ---------------------------------------------------------------------------
// packed f32x2 helpers (sm_103a FFMA2 path — only reachable via PTX)
// ---------------------------------------------------------------------------
__device__ __forceinline__ float2 ffma2(float2 a, float2 b, float2 c) {
    float2 d;
    asm("fma.rn.f32x2 %0, %1, %2, %3;"
        : "=l"(reinterpret_cast<unsigned long long&>(d))
        : "l"(reinterpret_cast<unsigned long long&>(a)),
          "l"(reinterpret_cast<unsigned long long&>(b)),
          "l"(reinterpret_cast<unsigned long long&>(c)));
    return d;
}
__device__ __forceinline__ float2 fmul2(float2 a, float2 b) {
    float2 d;
    asm("mul.rn.f32x2 %0, %1, %2;"
        : "=l"(reinterpret_cast<unsigned long long&>(d))
        : "l"(reinterpret_cast<unsigned long long&>(a)),
          "l"(reinterpret_cast<unsigned long long&>(b)));
    return d;
}
__device__ __forceinline__ float2 fadd2(float2 a, float2 b) {
    float2 d;
    asm("add.rn.f32x2 %0, %1, %2;"
        : "=l"(reinterpret_cast<unsigned long long&>(d))
        : "l"(reinterpret_cast<unsigned long long&>(a)),
          "l"(reinterpret_cast<unsigned long long&>(b)));
    return d;
}

// ---------------------------------------------------------------------------
// Prep kernel: C[f] = sum_n coeffs[n][f], then convert Chebyshev T_0..T_7
// coefficients of each input to even/odd monomial-in-y (y = x^2) Horner
// coefficients, and scatter into the packed layout above.
// grid = 64 blocks * 256 threads; block handles 32 features = 4 inputs.
// ---------------------------------------------------------------------------
__global__ void kan_prep(const float* __restrict__ coeffs) {
    __shared__ float sh[8][32];
    __shared__ float cs[32];
    const int t  = threadIdx.x;
    const int fl = t & 31;        // feature within block
    const int g  = t >> 5;        // neuron group (8 groups of 16)
    const int f  = blockIdx.x * 32 + fl;

    float s = 0.0f;
#pragma unroll
    for (int n = 0; n < 16; n++)
        s += coeffs[(g * 16 + n) * NFEAT + f];
    sh[g][fl] = s;
    __syncthreads();

    if (t < 32) {
        float c = 0.0f;
#pragma unroll
        for (int gg = 0; gg < 8; gg++) c += sh[gg][t];
        cs[t] = c;
    }
    __syncthreads();

    if (t < 4) {
        const int i = blockIdx.x * 4 + t;   // global input index
        float C[8];
#pragma unroll
        for (int d = 0; d < 8; d++) C[d] = cs[t * 8 + d];

        // T0=1; T1=x; T2=2y-1; T3=x(4y-3); T4=8y^2-8y+1; T5=x(16y^2-20y+5)
        // T6=32y^3-48y^2+18y-1; T7=x(64y^3-112y^2+56y-7)   (y = x^2)
        float cf[8];
        cf[0] = C[0] - C[2] + C[4] - C[6];           // e0
        cf[1] = 2.f*C[2] - 8.f*C[4] + 18.f*C[6];     // e1
        cf[2] = 8.f*C[4] - 48.f*C[6];                // e2
        cf[3] = 32.f*C[6];                           // e3
        cf[4] = C[1] - 3.f*C[3] + 5.f*C[5] - 7.f*C[7];   // o0
        cf[5] = 4.f*C[3] - 20.f*C[5] + 56.f*C[7];        // o1
        cf[6] = 16.f*C[5] - 112.f*C[7];                  // o2
        cf[7] = 64.f*C[7];                               // o3

        const int p    = i >> 1;       // pair index
        const int lane = p >> 2;       // owning lane
        const int q    = p & 3;        // pair-within-lane
        const int e    = i & 1;        // element within pair
#pragma unroll
        for (int j = 0; j < 8; j++) {
            const int gj = j >> 1;
            g_pack[((q * 4 + gj) * 32 + lane) * 4 + (j & 1) * 2 + e] = cf[j];
        }
    }
}

// ---------------------------------------------------------------------------
// Main kernel: one warp handles 4 rows. Lane owns inputs [lane*8, lane*8+8).
// grid = 1024 blocks * 256 threads (8 warps) -> 1024*8*4 = 32768 rows.
// ---------------------------------------------------------------------------
__global__ __launch_bounds__(256, 2)
void kan_main(const float* __restrict__ x, float* __restrict__ out) {
    const int lane = threadIdx.x & 31;
    const int w    = threadIdx.x >> 5;
    const int row0 = (blockIdx.x * 8 + w) * 4;

    // Coefficient load: 16 coalesced LDG.128 of the 8 KB L1/L2-resident table.
    const float4* __restrict__ cp = reinterpret_cast<const float4*>(g_pack);
    float4 v[16];
#pragma unroll
    for (int m = 0; m < 16; m++) v[m] = cp[m * 32 + lane];

    // Prefetch x for all 4 rows: 8 coalesced LDG.128.
    const float4* __restrict__ xr = reinterpret_cast<const float4*>(x);
    float4 xa[4], xb[4];
#pragma unroll
    for (int r = 0; r < 4; r++) {
        const int base = (row0 + r) * (INPUT_DIM / 4) + lane * 2;
        xa[r] = xr[base];
        xb[r] = xr[base + 1];
    }

#pragma unroll
    for (int r = 0; r < 4; r++) {
        float2 xp[4];
        xp[0] = make_float2(xa[r].x, xa[r].y);
        xp[1] = make_float2(xa[r].z, xa[r].w);
        xp[2] = make_float2(xb[r].x, xb[r].y);
        xp[3] = make_float2(xb[r].z, xb[r].w);

        float2 acc = make_float2(0.0f, 0.0f);
#pragma unroll
        for (int q = 0; q < 4; q++) {
            const float2 X = xp[q];
            const float2 Y = fmul2(X, X);
            const float4 g0 = v[q * 4 + 0];   // (e0, e1)
            const float4 g1 = v[q * 4 + 1];   // (e2, e3)
            const float4 g2 = v[q * 4 + 2];   // (o0, o1)
            const float4 g3 = v[q * 4 + 3];   // (o2, o3)
            const float2 e0 = make_float2(g0.x, g0.y), e1 = make_float2(g0.z, g0.w);
            const float2 e2 = make_float2(g1.x, g1.y), e3 = make_float2(g1.z, g1.w);
            const float2 o0 = make_float2(g2.x, g2.y), o1 = make_float2(g2.z, g2.w);
            const float2 o2 = make_float2(g3.x, g3.y), o3 = make_float2(g3.z, g3.w);

            float2 ev = ffma2(e3, Y, e2);
            ev = ffma2(ev, Y, e1);
            ev = ffma2(ev, Y, e0);
            float2 od = ffma2(o3, Y, o2);
            od = ffma2(od, Y, o1);
            od = ffma2(od, Y, o0);

            acc = fadd2(acc, ev);
            acc = ffma2(od, X, acc);
        }
        float s = acc.x + acc.y;
#pragma unroll
        for (int off = 16; off; off >>= 1)
            s += __shfl_xor_sync(0xffffffffu, s, off);
        if (lane == 0) out[row0 + r] = s;
    }
}

// ---------------------------------------------------------------------------
extern "C" void kernel_launch(void* const* d_in, const int* in_sizes, int n_in,
                              void* d_out, int out_size) {
    const float* x      = (const float*)d_in[0];   // [32768, 256]
    const float* coeffs = (const float*)d_in[1];   // [128, 2048]
    float* out          = (float*)d_out;           // [32768, 1]
    (void)in_sizes; (void)n_in; (void)out_size;

    kan_prep<<<NFEAT / 32, 256>>>(coeffs);
    kan_main<<<BATCH / 32, 256>>>(x, out);
}

// round 2
// speedup vs baseline: 1.1946x; 1.1946x over previous
#include <cuda_runtime.h>
#include <cuda_bf16.h>

// Problem constants
#define BATCH      32768
#define INPUT_DIM  256
#define NNEUR      128
#define NDEG       8                     // D+1 coefficients per input dim
#define NFEAT      (INPUT_DIM * NDEG)    // 2048
#define NGROUPS    (BATCH / 4)           // row-groups of 4

#define GRID_MAIN  304                   // 152 SMs x 2 resident blocks
#define THREADS    256

// Transformed + packed coefficient table (8 KB), produced by kan_prep.
// Granule linear index m in [0,512): m = (q*4 + gj)*32 + lane.
// Lane owns inputs i = lane*8 .. lane*8+7 (pairs p = lane*4+q).
// Granule gj of pair p holds coefficients (c_{2gj}, c_{2gj+1}) for both
// inputs of the pair: [ c_{2gj}(i0), c_{2gj}(i1), c_{2gj+1}(i0), c_{2gj+1}(i1) ].
// Coefficient order c_0..c_7 = e0,e1,e2,e3,o0,o1,o2,o3 (even/odd Horner).
__device__ float g_pack[NFEAT];

// ---------------------------------------------------------------------------
// packed f32x2 helpers (sm_103a FFMA2 path — only reachable via PTX)
// ---------------------------------------------------------------------------
__device__ __forceinline__ float2 ffma2(float2 a, float2 b, float2 c) {
    float2 d;
    asm("fma.rn.f32x2 %0, %1, %2, %3;"
        : "=l"(reinterpret_cast<unsigned long long&>(d))
        : "l"(reinterpret_cast<unsigned long long&>(a)),
          "l"(reinterpret_cast<unsigned long long&>(b)),
          "l"(reinterpret_cast<unsigned long long&>(c)));
    return d;
}
__device__ __forceinline__ float2 fmul2(float2 a, float2 b) {
    float2 d;
    asm("mul.rn.f32x2 %0, %1, %2;"
        : "=l"(reinterpret_cast<unsigned long long&>(d))
        : "l"(reinterpret_cast<unsigned long long&>(a)),
          "l"(reinterpret_cast<unsigned long long&>(b)));
    return d;
}
__device__ __forceinline__ float2 fadd2(float2 a, float2 b) {
    float2 d;
    asm("add.rn.f32x2 %0, %1, %2;"
        : "=l"(reinterpret_cast<unsigned long long&>(d))
        : "l"(reinterpret_cast<unsigned long long&>(a)),
          "l"(reinterpret_cast<unsigned long long&>(b)));
    return d;
}

// ---------------------------------------------------------------------------
// Prep kernel: C[f] = sum_n coeffs[n][f], convert Chebyshev T_0..T_7 coeffs
// per input to even/odd y-Horner (y = x^2) coeffs, scatter into g_pack.
// grid = 128 blocks x 256 threads; block handles 16 features = 2 inputs.
// Thread layout: fl = t & 15 (feature), g = t >> 4 (16 groups of 8 neurons).
// ---------------------------------------------------------------------------
__global__ void kan_prep(const float* __restrict__ coeffs) {
    __shared__ float sh[16][16];
    __shared__ float cs[16];
    const int t  = threadIdx.x;
    const int fl = t & 15;
    const int g  = t >> 4;
    const int f  = blockIdx.x * 16 + fl;

    float s = 0.0f;
#pragma unroll
    for (int n = 0; n < 8; n++)
        s += coeffs[(g * 8 + n) * NFEAT + f];
    sh[g][fl] = s;
    __syncthreads();

    if (t < 16) {
        float c = 0.0f;
#pragma unroll
        for (int gg = 0; gg < 16; gg++) c += sh[gg][t];
        cs[t] = c;
    }
    __syncthreads();

    if (t < 2) {
        const int i = blockIdx.x * 2 + t;   // global input index
        float C[8];
#pragma unroll
        for (int d = 0; d < 8; d++) C[d] = cs[t * 8 + d];

        // T0=1; T1=x; T2=2y-1; T3=x(4y-3); T4=8y^2-8y+1; T5=x(16y^2-20y+5)
        // T6=32y^3-48y^2+18y-1; T7=x(64y^3-112y^2+56y-7)   (y = x^2)
        float cf[8];
        cf[0] = C[0] - C[2] + C[4] - C[6];               // e0
        cf[1] = 2.f*C[2] - 8.f*C[4] + 18.f*C[6];         // e1
        cf[2] = 8.f*C[4] - 48.f*C[6];                    // e2
        cf[3] = 32.f*C[6];                               // e3
        cf[4] = C[1] - 3.f*C[3] + 5.f*C[5] - 7.f*C[7];   // o0
        cf[5] = 4.f*C[3] - 20.f*C[5] + 56.f*C[7];        // o1
        cf[6] = 16.f*C[5] - 112.f*C[7];                  // o2
        cf[7] = 64.f*C[7];                               // o3

        const int p    = i >> 1;       // pair index
        const int lane = p >> 2;       // owning lane
        const int q    = p & 3;        // pair-within-lane
        const int e    = i & 1;        // element within pair
#pragma unroll
        for (int j = 0; j < 8; j++) {
            const int gj = j >> 1;
            g_pack[((q * 4 + gj) * 32 + lane) * 4 + (j & 1) * 2 + e] = cf[j];
        }
    }
}

// ---------------------------------------------------------------------------
// Main kernel: PERSISTENT. 304 blocks x 256 threads; each warp grid-strides
// over row-groups of 4. Coefficients live in registers for the whole kernel.
// Lane owns inputs [lane*8, lane*8+8) of each row it touches.
// ---------------------------------------------------------------------------
__global__ __launch_bounds__(THREADS, 2)
void kan_main(const float* __restrict__ x, float* __restrict__ out) {
    const int lane    = threadIdx.x & 31;
    const int w       = threadIdx.x >> 5;
    const int warpId  = blockIdx.x * (THREADS / 32) + w;
    const int nWarps  = GRID_MAIN * (THREADS / 32);

    // Coefficient load: 16 coalesced LDG.128 of the 8 KB L1/L2-resident
    // table, done ONCE per warp for its whole lifetime.
    const float4* __restrict__ cp = reinterpret_cast<const float4*>(g_pack);
    float4 v[16];
#pragma unroll
    for (int m = 0; m < 16; m++) v[m] = cp[m * 32 + lane];

    const float4* __restrict__ xr = reinterpret_cast<const float4*>(x);

    for (int grp = warpId; grp < NGROUPS; grp += nWarps) {
        const int row0 = grp * 4;

        // 8 coalesced LDG.128 for 4 rows (all independent -> MLP 8).
        float4 xa[4], xb[4];
#pragma unroll
        for (int r = 0; r < 4; r++) {
            const int base = (row0 + r) * (INPUT_DIM / 4) + lane * 2;
            xa[r] = xr[base];
            xb[r] = xr[base + 1];
        }

#pragma unroll
        for (int r = 0; r < 4; r++) {
            float2 xp[4];
            xp[0] = make_float2(xa[r].x, xa[r].y);
            xp[1] = make_float2(xa[r].z, xa[r].w);
            xp[2] = make_float2(xb[r].x, xb[r].y);
            xp[3] = make_float2(xb[r].z, xb[r].w);

            float2 acc = make_float2(0.0f, 0.0f);
#pragma unroll
            for (int q = 0; q < 4; q++) {
                const float2 X = xp[q];
                const float2 Y = fmul2(X, X);
                const float4 g0 = v[q * 4 + 0];   // (e0, e1)
                const float4 g1 = v[q * 4 + 1];   // (e2, e3)
                const float4 g2 = v[q * 4 + 2];   // (o0, o1)
                const float4 g3 = v[q * 4 + 3];   // (o2, o3)
                const float2 e0 = make_float2(g0.x, g0.y), e1 = make_float2(g0.z, g0.w);
                const float2 e2 = make_float2(g1.x, g1.y), e3 = make_float2(g1.z, g1.w);
                const float2 o0 = make_float2(g2.x, g2.y), o1 = make_float2(g2.z, g2.w);
                const float2 o2 = make_float2(g3.x, g3.y), o3 = make_float2(g3.z, g3.w);

                float2 ev = ffma2(e3, Y, e2);
                ev = ffma2(ev, Y, e1);
                ev = ffma2(ev, Y, e0);
                float2 od = ffma2(o3, Y, o2);
                od = ffma2(od, Y, o1);
                od = ffma2(od, Y, o0);

                acc = fadd2(acc, ev);
                acc = ffma2(od, X, acc);
            }
            float s = acc.x + acc.y;
#pragma unroll
            for (int off = 16; off; off >>= 1)
                s += __shfl_xor_sync(0xffffffffu, s, off);
            if (lane == 0) out[row0 + r] = s;
        }
    }
}

// ---------------------------------------------------------------------------
extern "C" void kernel_launch(void* const* d_in, const int* in_sizes, int n_in,
                              void* d_out, int out_size) {
    const float* x      = (const float*)d_in[0];   // [32768, 256]
    const float* coeffs = (const float*)d_in[1];   // [128, 2048]
    float* out          = (float*)d_out;           // [32768, 1]
    (void)in_sizes; (void)n_in; (void)out_size;

    kan_prep<<<NFEAT / 16, 256>>>(coeffs);
    kan_main<<<GRID_MAIN, THREADS>>>(x, out);
}